// round 11
// baseline (speedup 1.0000x reference)
#include <cuda_runtime.h>
#include <math.h>

// ---------------- static configuration ----------------
#define Bn     32
#define Tn     4096
#define Cn     3
#define NSC    128
#define NPSI   4096
#define PADL   2047
#define LP     8190           // Tn + 2*PADL
#define DXSTR  8192
#define NROW   96             // Cn * Bn
#define OUTH   224
#define OUTW   224
#define OUTN   (Bn*OUTH*OUTW*Cn)

#define U0     384            // global u-grid origin
#define KE     3456           // Ê u-extent
#define MTOT   896            // 128 scales x 7 interior classes
#define KMAX   3268           // >= max wavelet kernel length 3265
#define KSTR   3280           // g_kern row stride
#define EKE    3328           // edge-kernel stride (fixup)

#define BM     128
#define BN     64
#define BK     16
#define SAST   132
#define SBST   68
#define KC     512            // split-K chunk (32 k-steps)
#define MAXCH  26             // chunk table capacity (real ~19)
#define NTOTAL 3072           // 96 rows x 32 j
#define GRIDP  592            // persistent gemm blocks (4/SM x 148)
#define DXTOT  (NROW * DXSTR)

// ---------------- device scratch ----------------
__device__ __align__(16) float g_dx[DXTOT + 4096];             // 3 MB (zero-init)
__device__ __align__(16) float g_kern[NSC * KSTR];             // 1.7 MB gathered kernels
__device__ __align__(16) float g_eh[(size_t)MTOT * KE + 64];   // 12.4 MB [m][k]
__device__ __align__(16) float g_ehT[(size_t)KE * MTOT + 64];  // 12.4 MB [k][m]
__device__ __align__(16) float g_eke[NSC * 2 * EKE];           // 3.4 MB edge kernels
__device__ __align__(16) float g_part[(size_t)MAXCH * BM * NTOTAL]; // 41 MB partials
__device__ float  g_tmpA[NSC * NROW * OUTW];                   // 11 MB [sc][row][w]
__device__ int    g_n[NSC];
__device__ int    g_d0[NSC];
__device__ float  g_nsq[NSC];
__device__ float  g_wt[OUTW * 40];
__device__ int    g_wst[OUTW];
__device__ int    g_wcnt[OUTW];
__device__ int    g_whi[OUTH * 2];
__device__ float  g_whw[OUTH * 2];
__device__ int    g_tk[7 * 2];
__device__ int    g_chk[MAXCH * 2];                            // chunk -> (mt, klo)
__device__ int    g_chklen[MAXCH];
__device__ int    g_nchk;
__device__ int    g_tfirst[7];
__device__ int    g_tcnt[7];
__device__ int    g_nitems;
__device__ unsigned int g_tick;

// ---------------- per-scale parameters (exact double formula) ----------------
__device__ __forceinline__ void scale_param(int s, int* n_out, int* d0_out,
                                            double* den_out, float* sf_out) {
    double l2 = log10(2.0), lM = log10(204.0);
    double y = (s == NSC - 1) ? lM : (l2 + (double)s * ((lM - l2) / (double)(NSC - 1)));
    float  sf = (float)pow(10.0, y);
    double sd = (double)sf;
    int n = (int)ceil(sd * 16.0 + 1.0);
    int d0 = (4094 - n) / 2; if (d0 < 0) d0 = 0;
    *n_out = n; *d0_out = d0;
    if (den_out) *den_out = sd * (16.0 / 4095.0);
    if (sf_out)  *sf_out = sf;
}

// ---------------- setup + gather (grid = 128 blocks, one per scale) ----------------
__global__ __launch_bounds__(256) void k_setup(const float* __restrict__ psi) {
    int sc = blockIdx.x;
    int tid = threadIdx.x;

    int n, d0; double den; float sf;
    scale_param(sc, &n, &d0, &den, &sf);
    if (tid == 0) {
        g_n[sc] = n; g_d0[sc] = d0; g_nsq[sc] = -sqrtf(sf);
    }
    for (int k = tid; k < n; k += 256) {
        int m = n - 1 - k;                                  // flip
        int j = (int)floor((double)m / den);
        if (j < 0) j = 0;
        if (j > NPSI - 1) j = NPSI - 1;
        g_kern[sc * KSTR + k] = psi[j];
    }
    if (blockIdx.x != 0) return;

    if (tid < OUTW) {
        double inv = 4096.0 / 224.0;
        double ks  = inv;
        double sfd = ((double)tid + 0.5) * inv - 0.5;
        int lo = (int)ceil(sfd - ks);  if (lo < 0) lo = 0;
        int hi = (int)floor(sfd + ks); if (hi > Tn - 1) hi = Tn - 1;
        double tot = 0.0;
        for (int i = lo; i <= hi; i++) {
            double w = 1.0 - fabs((double)i - sfd) / ks; if (w < 0.0) w = 0.0;
            tot += w;
        }
        int cnt = hi - lo + 1;
        g_wst[tid] = lo; g_wcnt[tid] = cnt;
        for (int j = 0; j < cnt; j++) {
            double w = 1.0 - fabs((double)(lo + j) - sfd) / ks; if (w < 0.0) w = 0.0;
            g_wt[tid * 40 + j] = (float)(w / tot);
        }
        for (int j = cnt; j < 40; j++) g_wt[tid * 40 + j] = 0.0f;
    }
    if (tid < OUTH) {
        double inv = 128.0 / 224.0;
        double sfd = ((double)tid + 0.5) * inv - 0.5;
        int ia = (int)floor(sfd);
        int i0 = ia, i1 = ia + 1;
        double w0 = 1.0 - (sfd - (double)ia);
        double w1 = sfd - (double)ia;
        bool v0 = (i0 >= 0 && i0 < NSC);
        bool v1 = (i1 >= 0 && i1 < NSC);
        double tot = (v0 ? w0 : 0.0) + (v1 ? w1 : 0.0);
        int   o0 = v0 ? i0 : (v1 ? i1 : 0);
        int   o1 = v1 ? i1 : (v0 ? i0 : 0);
        float f0 = v0 ? (float)(w0 / tot) : 0.0f;
        float f1 = v1 ? (float)(w1 / tot) : 0.0f;
        if (!v0 && v1) { f0 = (float)(w1 / tot); f1 = 0.0f; }
        g_whi[tid * 2 + 0] = o0; g_whi[tid * 2 + 1] = o1;
        g_whw[tid * 2 + 0] = f0; g_whw[tid * 2 + 1] = f1;
    }
    __syncthreads();
    if (tid < 7) {
        int smin = (BM * tid) / 7;
        int smax = (BM * tid + BM - 1) / 7; if (smax > NSC - 1) smax = NSC - 1;
        int lo = 1 << 30, hi = 0;
        for (int s = smin; s <= smax; s++) {
            int ns, ds; scale_param(s, &ns, &ds, 0, 0);
            for (int c = 0; c < 7; c++) {
                int A = ds + g_wst[7 + c] - 128;
                int e = A + ns + g_wcnt[7 + c] - 1;
                int a0 = A - U0, e0 = e + 1 - U0;
                if (a0 < lo) lo = a0;
                if (e0 > hi) hi = e0;
            }
        }
        g_tk[tid * 2 + 0] = lo & ~15;
        g_tk[tid * 2 + 1] = (hi + 15) & ~15;
    }
    __syncthreads();
    if (tid == 0) {
        int nc = 0;
        for (int q = 0; q < 7; q++) {
            int mt = 6 - q;                       // heavy tiles first
            int klo = g_tk[mt * 2], khi = g_tk[mt * 2 + 1];
            g_tfirst[mt] = nc;
            int cnt = 0;
            for (int k = klo; k < khi && nc < MAXCH; k += KC) {
                int len = khi - k; if (len > KC) len = KC;
                g_chk[nc * 2 + 0] = mt;
                g_chk[nc * 2 + 1] = k;
                g_chklen[nc] = len;
                nc++; cnt++;
            }
            g_tcnt[mt] = cnt;
        }
        g_nchk = nc;
        g_nitems = nc * 48;
        g_tick = 0u;
    }
}

// ---------------- dx helper ----------------
__device__ __forceinline__ float xp_val(const float* __restrict__ x, int b, int c, int p) {
    int i = p - PADL;
    if (i < 0) i = -i;
    else if (i >= Tn) i = 2 * (Tn - 1) - i;
    return x[((size_t)b * Tn + i) * Cn + c];
}

// ---------------- build resize-folded kernels + dx (fused, independent work) ----------------
__global__ __launch_bounds__(256) void k_ebuild(const float* __restrict__ x) {
    __shared__ float skern[KMAX];
    __shared__ float swt[40];
    int cls = blockIdx.x;
    int sc  = blockIdx.y;
    int tid = threadIdx.x;
    int bid = sc * 9 + cls;                                 // 0..1151

    // ---- dx slice (grid-stride over all 1152 blocks) ----
    for (int idx = bid * 256 + tid; idx < DXTOT; idx += 1152 * 256) {
        int r = idx >> 13;
        int p = idx & (DXSTR - 1);
        int c = r / Bn, b = r % Bn;
        float v = 0.0f;
        if (p <= LP - 2) v = xp_val(x, b, c, p + 1) - xp_val(x, b, c, p);
        g_dx[idx] = v;
    }

    int n = g_n[sc], d0 = g_d0[sc];
    float nsq = g_nsq[sc];
    int wrep = (cls < 7) ? (7 + cls) : ((cls == 7) ? 0 : 223);
    int st = g_wst[wrep], cnt = g_wcnt[wrep];

    for (int k = tid; k < n; k += 256) skern[k] = g_kern[sc * KSTR + k];
    if (tid < 40) swt[tid] = g_wt[wrep * 40 + tid];
    __syncthreads();

    int len = n + cnt - 1;
    if (cls < 7) {
        int A = d0 + st - 128;
        int m = sc * 7 + cls;
        int p0 = A - U0;
        float* dst = g_eh + (size_t)m * KE;
        for (int v = tid; v < KE; v += 256) {
            int p = v - p0;
            float acc = 0.0f;
            if (p >= 0 && p < len) {
                int t0 = p - (n - 1); if (t0 < 0) t0 = 0;
                int t1 = p; if (t1 > cnt - 1) t1 = cnt - 1;
                for (int t = t0; t <= t1; t++) acc += swt[t] * skern[p - t];
                acc *= nsq;
            }
            dst[v] = acc;
        }
    } else {
        int sh = (d0 + st) & 3;
        float* dst = g_eke + (size_t)(sc * 2 + (cls - 7)) * EKE;
        for (int v = tid; v < EKE; v += 256) {
            int p = v - sh;
            float acc = 0.0f;
            if (p >= 0 && p < len) {
                int t0 = p - (n - 1); if (t0 < 0) t0 = 0;
                int t1 = p; if (t1 > cnt - 1) t1 = cnt - 1;
                for (int t = t0; t <= t1; t++) acc += swt[t] * skern[p - t];
                acc *= nsq;
            }
            dst[v] = acc;
        }
    }
}

// ---------------- transpose g_eh [m][k] -> g_ehT [k][m] ----------------
__global__ __launch_bounds__(256) void k_trans() {
    __shared__ float t[32][33];
    int k0 = blockIdx.x * 32;
    int m0 = blockIdx.y * 32;
    int tx = threadIdx.x & 31;
    int ty = threadIdx.x >> 5;
    #pragma unroll
    for (int r = 0; r < 4; r++) {
        int m = m0 + ty + r * 8;
        t[ty + r * 8][tx] = g_eh[(size_t)m * KE + k0 + tx];
    }
    __syncthreads();
    #pragma unroll
    for (int r = 0; r < 4; r++) {
        int k = k0 + ty + r * 8;
        g_ehT[(size_t)k * MTOT + m0 + tx] = t[tx][ty + r * 8];
    }
}

// ---------------- persistent GEMM, KC=512, atomic work ticket ----------------
__global__ __launch_bounds__(128, 4) void k_gemm() {
    __shared__ float sA[2][BK][SAST];
    __shared__ float sB[2][BK][SBST];
    __shared__ int s_item;

    int tid = threadIdx.x;
    int warp = tid >> 5, lane = tid & 31;
    int wm = warp >> 1, wn = warp & 1;
    int lm = lane >> 2, ln = lane & 3;
    int m8 = wm * 64 + lm * 8;
    int n8 = wn * 32 + ln * 8;
    int mq = tid & 31, kA = tid >> 5;
    int nb = tid & 63, kh = tid >> 6;
    int nitems = g_nitems;

    while (true) {
        if (tid == 0) s_item = (int)atomicAdd(&g_tick, 1u);
        __syncthreads();
        int item = s_item;
        if (item >= nitems) return;

        int chunk = item / 48;
        int nt    = item - chunk * 48;
        int mt  = g_chk[chunk * 2 + 0];
        int klo = g_chk[chunk * 2 + 1];
        int nk  = g_chklen[chunk] >> 4;
        int m0 = mt * BM, n0 = nt * BN;
        int ng = n0 + nb; int brow = ng >> 5, bj = ng & 31;

        const float* pA = g_ehT + (size_t)(klo + kA) * MTOT + m0 + mq * 4;
        const float* pB = g_dx + (size_t)brow * DXSTR + U0 + klo + (bj << 7) + kh * 8;

        float4 Ar0, Ar1, Ar2, Ar3, Br0, Br1;
        Ar0 = *(const float4*)(pA);
        Ar1 = *(const float4*)(pA + (size_t)4 * MTOT);
        Ar2 = *(const float4*)(pA + (size_t)8 * MTOT);
        Ar3 = *(const float4*)(pA + (size_t)12 * MTOT);
        Br0 = *(const float4*)(pB);
        Br1 = *(const float4*)(pB + 4);
        {
            *(float4*)&sA[0][kA][mq * 4]      = Ar0;
            *(float4*)&sA[0][kA + 4][mq * 4]  = Ar1;
            *(float4*)&sA[0][kA + 8][mq * 4]  = Ar2;
            *(float4*)&sA[0][kA + 12][mq * 4] = Ar3;
            int k0 = kh * 8;
            sB[0][k0 + 0][nb] = Br0.x; sB[0][k0 + 1][nb] = Br0.y;
            sB[0][k0 + 2][nb] = Br0.z; sB[0][k0 + 3][nb] = Br0.w;
            sB[0][k0 + 4][nb] = Br1.x; sB[0][k0 + 5][nb] = Br1.y;
            sB[0][k0 + 6][nb] = Br1.z; sB[0][k0 + 7][nb] = Br1.w;
        }
        __syncthreads();

        float acc[8][8];
        #pragma unroll
        for (int i = 0; i < 8; i++)
            #pragma unroll
            for (int j = 0; j < 8; j++) acc[i][j] = 0.f;

        for (int kb = 0; kb < nk; kb++) {
            int cur = kb & 1;
            if (kb + 1 < nk) {
                const float* qA = pA + (size_t)(kb + 1) * BK * MTOT;
                const float* qB = pB + (kb + 1) * BK;
                Ar0 = *(const float4*)(qA);
                Ar1 = *(const float4*)(qA + (size_t)4 * MTOT);
                Ar2 = *(const float4*)(qA + (size_t)8 * MTOT);
                Ar3 = *(const float4*)(qA + (size_t)12 * MTOT);
                Br0 = *(const float4*)(qB);
                Br1 = *(const float4*)(qB + 4);
            }
            #pragma unroll
            for (int k = 0; k < BK; k++) {
                float a[8], b[8];
                *(float4*)(a)     = *(const float4*)&sA[cur][k][m8];
                *(float4*)(a + 4) = *(const float4*)&sA[cur][k][m8 + 4];
                *(float4*)(b)     = *(const float4*)&sB[cur][k][n8];
                *(float4*)(b + 4) = *(const float4*)&sB[cur][k][n8 + 4];
                #pragma unroll
                for (int i = 0; i < 8; i++)
                    #pragma unroll
                    for (int j = 0; j < 8; j++)
                        acc[i][j] = fmaf(a[i], b[j], acc[i][j]);
            }
            if (kb + 1 < nk) {
                int nx = cur ^ 1;
                *(float4*)&sA[nx][kA][mq * 4]      = Ar0;
                *(float4*)&sA[nx][kA + 4][mq * 4]  = Ar1;
                *(float4*)&sA[nx][kA + 8][mq * 4]  = Ar2;
                *(float4*)&sA[nx][kA + 12][mq * 4] = Ar3;
                int k0 = kh * 8;
                sB[nx][k0 + 0][nb] = Br0.x; sB[nx][k0 + 1][nb] = Br0.y;
                sB[nx][k0 + 2][nb] = Br0.z; sB[nx][k0 + 3][nb] = Br0.w;
                sB[nx][k0 + 4][nb] = Br1.x; sB[nx][k0 + 5][nb] = Br1.y;
                sB[nx][k0 + 6][nb] = Br1.z; sB[nx][k0 + 7][nb] = Br1.w;
            }
            __syncthreads();
        }

        float* pp = g_part + ((size_t)chunk * BM) * NTOTAL;
        #pragma unroll
        for (int i = 0; i < 8; i++) {
            float* row = pp + (size_t)(m8 + i) * NTOTAL + n0 + n8;
            float4 v0 = make_float4(acc[i][0], acc[i][1], acc[i][2], acc[i][3]);
            float4 v1 = make_float4(acc[i][4], acc[i][5], acc[i][6], acc[i][7]);
            *(float4*)(row)     = v0;
            *(float4*)(row + 4) = v1;
        }
        __syncthreads();
    }
}

// ---------------- fused split-K reduction + permute into g_tmpA ----------------
__global__ __launch_bounds__(224) void k_redtr2() {
    __shared__ float sm[224];
    int sc  = blockIdx.x;
    int row = blockIdx.y;
    int t = threadIdx.x;
    int cc = t >> 5, jj = t & 31;
    int m = sc * 7 + cc;
    int mt = m >> 7, ml = m & 127;
    int first = g_tfirst[mt], cnt = g_tcnt[mt];
    float s = 0.f;
    for (int c = 0; c < cnt; c++)
        s += g_part[((size_t)(first + c) * BM + ml) * NTOTAL + row * 32 + jj];
    sm[cc * 32 + jj] = s;
    __syncthreads();
    int w = t;
    if (w != 0 && w != 223) {                    // edges owned by k_fixup
        int j2 = w / 7, c2 = w - j2 * 7;
        g_tmpA[(sc * NROW + row) * OUTW + w] = sm[c2 * 32 + j2];
    }
}

// ---------------- exact fixup for clipped edge columns w=0, w=223 (R9 version) ----------------
__global__ void k_fixup() {
    __shared__ float se[EKE];
    int e  = blockIdx.x;
    int sc = blockIdx.y;
    int tid = threadIdx.x;
    int wE = e ? 223 : 0;
    int n = g_n[sc], d0 = g_d0[sc];
    int st = g_wst[wE], cnt = g_wcnt[wE];
    int base = (d0 + st) & ~3;
    int sh = (d0 + st) & 3;
    int qmax = sh + n + cnt - 1;

    const float* esrc = g_eke + (size_t)(sc * 2 + e) * EKE;
    for (int i = tid * 4; i < EKE; i += 1024)
        *(float4*)(se + i) = *(const float4*)(esrc + i);
    __syncthreads();

    int wi = tid >> 5, lane = tid & 31;
    for (int row = wi; row < NROW; row += 8) {
        const float* dxr = g_dx + (size_t)row * DXSTR + base;
        float p = 0.f;
        for (int q = lane * 4; q < qmax; q += 128) {
            float4 d = *(const float4*)(dxr + q);
            float4 ev = *(const float4*)(se + q);
            p = fmaf(d.x, ev.x, fmaf(d.y, ev.y, fmaf(d.z, ev.z, fmaf(d.w, ev.w, p))));
        }
        #pragma unroll
        for (int o = 16; o > 0; o >>= 1) p += __shfl_xor_sync(0xffffffffu, p, o);
        if (lane == 0) g_tmpA[(sc * NROW + row) * OUTW + wE] = p;
    }
}

// ---------------- resize stage B: scale axis 128 -> 224 ----------------
__global__ void k_resize_h(float* __restrict__ out) {
    int idx = blockIdx.x * blockDim.x + threadIdx.x;
    if (idx >= OUTN) return;
    int c = idx % Cn;
    int w = (idx / Cn) % OUTW;
    int h = (idx / (Cn * OUTW)) % OUTH;
    int b = idx / (Cn * OUTW * OUTH);
    int i0 = g_whi[h * 2 + 0], i1 = g_whi[h * 2 + 1];
    float f0 = g_whw[h * 2 + 0], f1 = g_whw[h * 2 + 1];
    int rb = (c * Bn + b) * OUTW + w;
    out[idx] = f0 * g_tmpA[i0 * NROW * OUTW + rb] + f1 * g_tmpA[i1 * NROW * OUTW + rb];
}

// ---------------- launch ----------------
extern "C" void kernel_launch(void* const* d_in, const int* in_sizes, int n_in,
                              void* d_out, int out_size) {
    const float* x   = (const float*)d_in[0];       // (32, 4096, 3) f32
    const float* psi = (const float*)d_in[1];       // (4096,) f32
    float* out = (float*)d_out;

    k_setup<<<NSC, 256>>>(psi);
    k_ebuild<<<dim3(9, NSC), 256>>>(x);              // also writes g_dx (grid-stride)
    k_trans<<<dim3(KE / 32, MTOT / 32), 256>>>();
    k_gemm<<<GRIDP, 128>>>();                        // launch index 3 -> ncu measures this
    k_redtr2<<<dim3(NSC, NROW), 224>>>();
    k_fixup<<<dim3(2, NSC), 256>>>();
    k_resize_h<<<(OUTN + 255) / 256, 256>>>(out);
}

// round 12
// speedup vs baseline: 1.0116x; 1.0116x over previous
#include <cuda_runtime.h>
#include <math.h>

// ---------------- static configuration ----------------
#define Bn     32
#define Tn     4096
#define Cn     3
#define NSC    128
#define NPSI   4096
#define PADL   2047
#define LP     8190           // Tn + 2*PADL
#define DXSTR  8192
#define NROW   96             // Cn * Bn
#define OUTH   224
#define OUTW   224
#define OUTN   (Bn*OUTH*OUTW*Cn)

#define U0     384            // global u-grid origin
#define KE     3456           // Ê u-extent
#define MTOT   896            // 128 scales x 7 interior classes
#define KMAX   3268           // >= max wavelet kernel length 3265
#define KSTR   3280           // g_kern row stride
#define EKE    3328           // edge-kernel stride (fixup)

#define BM     128
#define BN     64
#define BK     16
#define SAST   132
#define SBST   68
#define KC     512            // split-K chunk (32 k-steps)
#define MAXCH  26             // chunk table capacity (real ~19)
#define NTOTAL 3072           // 96 rows x 32 j
#define DXTOT  (NROW * DXSTR)
#define TRB    3024           // trans grid blocks (108 x 28)

// ---------------- device scratch ----------------
__device__ __align__(16) float g_dx[DXTOT + 4096];             // 3 MB (zero-init)
__device__ __align__(16) float g_kern[NSC * KSTR];             // 1.7 MB gathered kernels
__device__ __align__(16) float g_eh[(size_t)MTOT * KE + 64];   // 12.4 MB [m][k]
__device__ __align__(16) float g_ehT[(size_t)KE * MTOT + 64];  // 12.4 MB [k][m]
__device__ __align__(16) float g_eke[NSC * 2 * EKE];           // 3.4 MB edge kernels
__device__ __align__(16) float g_part[(size_t)MAXCH * BM * NTOTAL]; // 41 MB partials
__device__ float  g_tmpA[NSC * NROW * OUTW];                   // 11 MB [sc][row][w]
__device__ int    g_n[NSC];
__device__ int    g_d0[NSC];
__device__ float  g_nsq[NSC];
__device__ float  g_wt[OUTW * 40];
__device__ int    g_wst[OUTW];
__device__ int    g_wcnt[OUTW];
__device__ int    g_whi[OUTH * 2];
__device__ float  g_whw[OUTH * 2];
__device__ int    g_tk[7 * 2];
__device__ int    g_chk[MAXCH * 2];                            // chunk -> (mt, klo)
__device__ int    g_chklen[MAXCH];
__device__ int    g_nchk;
__device__ int    g_tfirst[7];
__device__ int    g_tcnt[7];

// ---------------- per-scale parameters (exact double formula) ----------------
__device__ __forceinline__ void scale_param(int s, int* n_out, int* d0_out,
                                            double* den_out, float* sf_out) {
    double l2 = log10(2.0), lM = log10(204.0);
    double y = (s == NSC - 1) ? lM : (l2 + (double)s * ((lM - l2) / (double)(NSC - 1)));
    float  sf = (float)pow(10.0, y);
    double sd = (double)sf;
    int n = (int)ceil(sd * 16.0 + 1.0);
    int d0 = (4094 - n) / 2; if (d0 < 0) d0 = 0;
    *n_out = n; *d0_out = d0;
    if (den_out) *den_out = sd * (16.0 / 4095.0);
    if (sf_out)  *sf_out = sf;
}

// ---------------- setup + gather (grid = 128 blocks, one per scale) ----------------
__global__ __launch_bounds__(256) void k_setup(const float* __restrict__ psi) {
    int sc = blockIdx.x;
    int tid = threadIdx.x;

    int n, d0; double den; float sf;
    scale_param(sc, &n, &d0, &den, &sf);
    if (tid == 0) {
        g_n[sc] = n; g_d0[sc] = d0; g_nsq[sc] = -sqrtf(sf);
    }
    for (int k = tid; k < n; k += 256) {
        int m = n - 1 - k;                                  // flip
        int j = (int)floor((double)m / den);
        if (j < 0) j = 0;
        if (j > NPSI - 1) j = NPSI - 1;
        g_kern[sc * KSTR + k] = psi[j];
    }
    if (blockIdx.x != 0) return;

    if (tid < OUTW) {
        double inv = 4096.0 / 224.0;
        double ks  = inv;
        double sfd = ((double)tid + 0.5) * inv - 0.5;
        int lo = (int)ceil(sfd - ks);  if (lo < 0) lo = 0;
        int hi = (int)floor(sfd + ks); if (hi > Tn - 1) hi = Tn - 1;
        double tot = 0.0;
        for (int i = lo; i <= hi; i++) {
            double w = 1.0 - fabs((double)i - sfd) / ks; if (w < 0.0) w = 0.0;
            tot += w;
        }
        int cnt = hi - lo + 1;
        g_wst[tid] = lo; g_wcnt[tid] = cnt;
        for (int j = 0; j < cnt; j++) {
            double w = 1.0 - fabs((double)(lo + j) - sfd) / ks; if (w < 0.0) w = 0.0;
            g_wt[tid * 40 + j] = (float)(w / tot);
        }
        for (int j = cnt; j < 40; j++) g_wt[tid * 40 + j] = 0.0f;
    }
    if (tid < OUTH) {
        double inv = 128.0 / 224.0;
        double sfd = ((double)tid + 0.5) * inv - 0.5;
        int ia = (int)floor(sfd);
        int i0 = ia, i1 = ia + 1;
        double w0 = 1.0 - (sfd - (double)ia);
        double w1 = sfd - (double)ia;
        bool v0 = (i0 >= 0 && i0 < NSC);
        bool v1 = (i1 >= 0 && i1 < NSC);
        double tot = (v0 ? w0 : 0.0) + (v1 ? w1 : 0.0);
        int   o0 = v0 ? i0 : (v1 ? i1 : 0);
        int   o1 = v1 ? i1 : (v0 ? i0 : 0);
        float f0 = v0 ? (float)(w0 / tot) : 0.0f;
        float f1 = v1 ? (float)(w1 / tot) : 0.0f;
        if (!v0 && v1) { f0 = (float)(w1 / tot); f1 = 0.0f; }
        g_whi[tid * 2 + 0] = o0; g_whi[tid * 2 + 1] = o1;
        g_whw[tid * 2 + 0] = f0; g_whw[tid * 2 + 1] = f1;
    }
    __syncthreads();
    if (tid < 7) {
        int smin = (BM * tid) / 7;
        int smax = (BM * tid + BM - 1) / 7; if (smax > NSC - 1) smax = NSC - 1;
        int lo = 1 << 30, hi = 0;
        for (int s = smin; s <= smax; s++) {
            int ns, ds; scale_param(s, &ns, &ds, 0, 0);
            for (int c = 0; c < 7; c++) {
                int A = ds + g_wst[7 + c] - 128;
                int e = A + ns + g_wcnt[7 + c] - 1;
                int a0 = A - U0, e0 = e + 1 - U0;
                if (a0 < lo) lo = a0;
                if (e0 > hi) hi = e0;
            }
        }
        g_tk[tid * 2 + 0] = lo & ~15;
        g_tk[tid * 2 + 1] = (hi + 15) & ~15;
    }
    __syncthreads();
    if (tid == 0) {
        int nc = 0;
        for (int q = 0; q < 7; q++) {
            int mt = 6 - q;                       // heavy tiles first
            int klo = g_tk[mt * 2], khi = g_tk[mt * 2 + 1];
            g_tfirst[mt] = nc;
            int cnt = 0;
            for (int k = klo; k < khi && nc < MAXCH; k += KC) {
                int len = khi - k; if (len > KC) len = KC;
                g_chk[nc * 2 + 0] = mt;
                g_chk[nc * 2 + 1] = k;
                g_chklen[nc] = len;
                nc++; cnt++;
            }
            g_tcnt[mt] = cnt;
        }
        g_nchk = nc;
    }
}

// ---------------- dx helper ----------------
__device__ __forceinline__ float xp_val(const float* __restrict__ x, int b, int c, int p) {
    int i = p - PADL;
    if (i < 0) i = -i;
    else if (i >= Tn) i = 2 * (Tn - 1) - i;
    return x[((size_t)b * Tn + i) * Cn + c];
}

// ---------------- build resize-folded kernels (plain R9 version) ----------------
__global__ __launch_bounds__(256) void k_ebuild() {
    __shared__ float skern[KMAX];
    __shared__ float swt[40];
    int cls = blockIdx.x;
    int sc  = blockIdx.y;
    int tid = threadIdx.x;
    int n = g_n[sc], d0 = g_d0[sc];
    float nsq = g_nsq[sc];
    int wrep = (cls < 7) ? (7 + cls) : ((cls == 7) ? 0 : 223);
    int st = g_wst[wrep], cnt = g_wcnt[wrep];

    for (int k = tid; k < n; k += 256) skern[k] = g_kern[sc * KSTR + k];
    if (tid < 40) swt[tid] = g_wt[wrep * 40 + tid];
    __syncthreads();

    int len = n + cnt - 1;
    if (cls < 7) {
        int A = d0 + st - 128;
        int m = sc * 7 + cls;
        int p0 = A - U0;
        float* dst = g_eh + (size_t)m * KE;
        for (int v = tid; v < KE; v += 256) {
            int p = v - p0;
            float acc = 0.0f;
            if (p >= 0 && p < len) {
                int t0 = p - (n - 1); if (t0 < 0) t0 = 0;
                int t1 = p; if (t1 > cnt - 1) t1 = cnt - 1;
                for (int t = t0; t <= t1; t++) acc += swt[t] * skern[p - t];
                acc *= nsq;
            }
            dst[v] = acc;
        }
    } else {
        int sh = (d0 + st) & 3;
        float* dst = g_eke + (size_t)(sc * 2 + (cls - 7)) * EKE;
        for (int v = tid; v < EKE; v += 256) {
            int p = v - sh;
            float acc = 0.0f;
            if (p >= 0 && p < len) {
                int t0 = p - (n - 1); if (t0 < 0) t0 = 0;
                int t1 = p; if (t1 > cnt - 1) t1 = cnt - 1;
                for (int t = t0; t <= t1; t++) acc += swt[t] * skern[p - t];
                acc *= nsq;
            }
            dst[v] = acc;
        }
    }
}

// ---------------- transpose g_eh [m][k] -> g_ehT [k][m]  +  dx (grid-stride) ----------------
__global__ __launch_bounds__(256) void k_transdx(const float* __restrict__ x) {
    __shared__ float t[32][33];
    int tid = threadIdx.x;
    int bid = blockIdx.y * gridDim.x + blockIdx.x;          // 0..3023

    // dx = diff(reflect_pad(x)) — independent of the transpose work
    for (int idx = bid * 256 + tid; idx < DXTOT; idx += TRB * 256) {
        int r = idx >> 13;
        int p = idx & (DXSTR - 1);
        int c = r / Bn, b = r % Bn;
        float v = 0.0f;
        if (p <= LP - 2) v = xp_val(x, b, c, p + 1) - xp_val(x, b, c, p);
        g_dx[idx] = v;
    }

    int k0 = blockIdx.x * 32;
    int m0 = blockIdx.y * 32;
    int tx = tid & 31;
    int ty = tid >> 5;
    #pragma unroll
    for (int r = 0; r < 4; r++) {
        int m = m0 + ty + r * 8;
        t[ty + r * 8][tx] = g_eh[(size_t)m * KE + k0 + tx];
    }
    __syncthreads();
    #pragma unroll
    for (int r = 0; r < 4; r++) {
        int k = k0 + ty + r * 8;
        g_ehT[(size_t)k * MTOT + m0 + tx] = t[tx][ty + r * 8];
    }
}

// ---------------- main GEMM (grid-launched split-K, R9 version) ----------------
__global__ __launch_bounds__(128, 4) void k_gemm() {
    int chunk = blockIdx.y;
    if (chunk >= g_nchk) return;
    int mt  = g_chk[chunk * 2 + 0];
    int klo = g_chk[chunk * 2 + 1];
    int nk  = g_chklen[chunk] >> 4;

    __shared__ float sA[2][BK][SAST];
    __shared__ float sB[2][BK][SBST];

    int nt = blockIdx.x;
    int m0 = mt * BM, n0 = nt * BN;
    int tid = threadIdx.x;
    int warp = tid >> 5, lane = tid & 31;
    int wm = warp >> 1, wn = warp & 1;
    int lm = lane >> 2, ln = lane & 3;
    int m8 = wm * 64 + lm * 8;
    int n8 = wn * 32 + ln * 8;

    int mq = tid & 31, kA = tid >> 5;
    int nb = tid & 63, kh = tid >> 6;
    int ng = n0 + nb; int brow = ng >> 5, bj = ng & 31;

    const float* pA = g_ehT + (size_t)(klo + kA) * MTOT + m0 + mq * 4;
    const float* pB = g_dx + (size_t)brow * DXSTR + U0 + klo + (bj << 7) + kh * 8;

    float4 Ar0, Ar1, Ar2, Ar3, Br0, Br1;
    Ar0 = *(const float4*)(pA);
    Ar1 = *(const float4*)(pA + (size_t)4 * MTOT);
    Ar2 = *(const float4*)(pA + (size_t)8 * MTOT);
    Ar3 = *(const float4*)(pA + (size_t)12 * MTOT);
    Br0 = *(const float4*)(pB);
    Br1 = *(const float4*)(pB + 4);
    {
        *(float4*)&sA[0][kA][mq * 4]      = Ar0;
        *(float4*)&sA[0][kA + 4][mq * 4]  = Ar1;
        *(float4*)&sA[0][kA + 8][mq * 4]  = Ar2;
        *(float4*)&sA[0][kA + 12][mq * 4] = Ar3;
        int k0 = kh * 8;
        sB[0][k0 + 0][nb] = Br0.x; sB[0][k0 + 1][nb] = Br0.y;
        sB[0][k0 + 2][nb] = Br0.z; sB[0][k0 + 3][nb] = Br0.w;
        sB[0][k0 + 4][nb] = Br1.x; sB[0][k0 + 5][nb] = Br1.y;
        sB[0][k0 + 6][nb] = Br1.z; sB[0][k0 + 7][nb] = Br1.w;
    }
    __syncthreads();

    float acc[8][8];
    #pragma unroll
    for (int i = 0; i < 8; i++)
        #pragma unroll
        for (int j = 0; j < 8; j++) acc[i][j] = 0.f;

    for (int kb = 0; kb < nk; kb++) {
        int cur = kb & 1;
        if (kb + 1 < nk) {
            const float* qA = pA + (size_t)(kb + 1) * BK * MTOT;
            const float* qB = pB + (kb + 1) * BK;
            Ar0 = *(const float4*)(qA);
            Ar1 = *(const float4*)(qA + (size_t)4 * MTOT);
            Ar2 = *(const float4*)(qA + (size_t)8 * MTOT);
            Ar3 = *(const float4*)(qA + (size_t)12 * MTOT);
            Br0 = *(const float4*)(qB);
            Br1 = *(const float4*)(qB + 4);
        }
        #pragma unroll
        for (int k = 0; k < BK; k++) {
            float a[8], b[8];
            *(float4*)(a)     = *(const float4*)&sA[cur][k][m8];
            *(float4*)(a + 4) = *(const float4*)&sA[cur][k][m8 + 4];
            *(float4*)(b)     = *(const float4*)&sB[cur][k][n8];
            *(float4*)(b + 4) = *(const float4*)&sB[cur][k][n8 + 4];
            #pragma unroll
            for (int i = 0; i < 8; i++)
                #pragma unroll
                for (int j = 0; j < 8; j++)
                    acc[i][j] = fmaf(a[i], b[j], acc[i][j]);
        }
        if (kb + 1 < nk) {
            int nx = cur ^ 1;
            *(float4*)&sA[nx][kA][mq * 4]      = Ar0;
            *(float4*)&sA[nx][kA + 4][mq * 4]  = Ar1;
            *(float4*)&sA[nx][kA + 8][mq * 4]  = Ar2;
            *(float4*)&sA[nx][kA + 12][mq * 4] = Ar3;
            int k0 = kh * 8;
            sB[nx][k0 + 0][nb] = Br0.x; sB[nx][k0 + 1][nb] = Br0.y;
            sB[nx][k0 + 2][nb] = Br0.z; sB[nx][k0 + 3][nb] = Br0.w;
            sB[nx][k0 + 4][nb] = Br1.x; sB[nx][k0 + 5][nb] = Br1.y;
            sB[nx][k0 + 6][nb] = Br1.z; sB[nx][k0 + 7][nb] = Br1.w;
        }
        __syncthreads();
    }

    float* pp = g_part + ((size_t)chunk * BM) * NTOTAL;
    #pragma unroll
    for (int i = 0; i < 8; i++) {
        float* row = pp + (size_t)(m8 + i) * NTOTAL + n0 + n8;
        float4 v0 = make_float4(acc[i][0], acc[i][1], acc[i][2], acc[i][3]);
        float4 v1 = make_float4(acc[i][4], acc[i][5], acc[i][6], acc[i][7]);
        *(float4*)(row)     = v0;
        *(float4*)(row + 4) = v1;
    }
}

// ---------------- fused split-K reduction + permute into g_tmpA ----------------
__global__ __launch_bounds__(224) void k_redtr2() {
    __shared__ float sm[224];
    int sc  = blockIdx.x;
    int row = blockIdx.y;
    int t = threadIdx.x;
    int cc = t >> 5, jj = t & 31;
    int m = sc * 7 + cc;
    int mt = m >> 7, ml = m & 127;
    int first = g_tfirst[mt], cnt = g_tcnt[mt];
    float s = 0.f;
    for (int c = 0; c < cnt; c++)
        s += g_part[((size_t)(first + c) * BM + ml) * NTOTAL + row * 32 + jj];
    sm[cc * 32 + jj] = s;
    __syncthreads();
    int w = t;
    if (w != 0 && w != 223) {                    // edges owned by k_fixup
        int j2 = w / 7, c2 = w - j2 * 7;
        g_tmpA[(sc * NROW + row) * OUTW + w] = sm[c2 * 32 + j2];
    }
}

// ---------------- exact fixup for clipped edge columns w=0, w=223 (R9 version) ----------------
__global__ void k_fixup() {
    __shared__ float se[EKE];
    int e  = blockIdx.x;
    int sc = blockIdx.y;
    int tid = threadIdx.x;
    int wE = e ? 223 : 0;
    int n = g_n[sc], d0 = g_d0[sc];
    int st = g_wst[wE], cnt = g_wcnt[wE];
    int base = (d0 + st) & ~3;
    int sh = (d0 + st) & 3;
    int qmax = sh + n + cnt - 1;

    const float* esrc = g_eke + (size_t)(sc * 2 + e) * EKE;
    for (int i = tid * 4; i < EKE; i += 1024)
        *(float4*)(se + i) = *(const float4*)(esrc + i);
    __syncthreads();

    int wi = tid >> 5, lane = tid & 31;
    for (int row = wi; row < NROW; row += 8) {
        const float* dxr = g_dx + (size_t)row * DXSTR + base;
        float p = 0.f;
        for (int q = lane * 4; q < qmax; q += 128) {
            float4 d = *(const float4*)(dxr + q);
            float4 ev = *(const float4*)(se + q);
            p = fmaf(d.x, ev.x, fmaf(d.y, ev.y, fmaf(d.z, ev.z, fmaf(d.w, ev.w, p))));
        }
        #pragma unroll
        for (int o = 16; o > 0; o >>= 1) p += __shfl_xor_sync(0xffffffffu, p, o);
        if (lane == 0) g_tmpA[(sc * NROW + row) * OUTW + wE] = p;
    }
}

// ---------------- resize stage B: scale axis 128 -> 224 ----------------
__global__ void k_resize_h(float* __restrict__ out) {
    int idx = blockIdx.x * blockDim.x + threadIdx.x;
    if (idx >= OUTN) return;
    int c = idx % Cn;
    int w = (idx / Cn) % OUTW;
    int h = (idx / (Cn * OUTW)) % OUTH;
    int b = idx / (Cn * OUTW * OUTH);
    int i0 = g_whi[h * 2 + 0], i1 = g_whi[h * 2 + 1];
    float f0 = g_whw[h * 2 + 0], f1 = g_whw[h * 2 + 1];
    int rb = (c * Bn + b) * OUTW + w;
    out[idx] = f0 * g_tmpA[i0 * NROW * OUTW + rb] + f1 * g_tmpA[i1 * NROW * OUTW + rb];
}

// ---------------- launch ----------------
extern "C" void kernel_launch(void* const* d_in, const int* in_sizes, int n_in,
                              void* d_out, int out_size) {
    const float* x   = (const float*)d_in[0];       // (32, 4096, 3) f32
    const float* psi = (const float*)d_in[1];       // (4096,) f32
    float* out = (float*)d_out;

    k_setup<<<NSC, 256>>>(psi);                      // 0: scales+gather+tables
    k_ebuild<<<dim3(9, NSC), 256>>>();               // 1: resize-folded kernels
    k_transdx<<<dim3(KE / 32, MTOT / 32), 256>>>(x); // 2: ehT transpose + dx
    k_gemm<<<dim3(48, MAXCH), 128>>>();              // 3: hot kernel (ncu slot)
    k_redtr2<<<dim3(NSC, NROW), 224>>>();            // 4: split-K reduce + permute
    k_fixup<<<dim3(2, NSC), 256>>>();                // 5: edge columns
    k_resize_h<<<(OUTN + 255) / 256, 256>>>(out);    // 6: scale-axis resize
}

// round 14
// speedup vs baseline: 1.4729x; 1.4560x over previous
#include <cuda_runtime.h>
#include <cuda_bf16.h>
#include <math.h>

// ---------------- static configuration ----------------
#define Bn     32
#define Tn     4096
#define Cn     3
#define NSC    128
#define NPSI   4096
#define PADL   2047
#define LP     8190           // Tn + 2*PADL
#define DXSTR  8192
#define NROW   96             // Cn * Bn
#define OUTH   224
#define OUTW   224
#define OUTN   (Bn*OUTH*OUTW*Cn)

#define U0     384            // global u-grid origin
#define KE     3456           // Ê u-extent (64-aligned)
#define MTOT   896            // 128 scales x 7 interior classes
#define KMAX   3268           // >= max wavelet kernel length 3265
#define KSTR   3280           // g_kern row stride
#define EKE    3328           // edge-kernel stride (fixup)

#define BM     128
#define BN     64
#define KC     512            // split-K chunk (16 slabs of 32)
#define MAXCH  26             // chunk table capacity (real ~19)
#define NTOTAL 3072           // 96 rows x 32 j
#define DXTOT  (NROW * DXSTR)

// ---------------- device scratch ----------------
__device__ __align__(16) float g_dx[DXTOT + 4096];                   // 3 MB f32 (fixup)
__device__ __align__(16) __nv_bfloat16 g_dxh[DXTOT + 4096];          // 1.5 MB
__device__ __align__(16) __nv_bfloat16 g_dxl[DXTOT + 4096];          // 1.5 MB
__device__ __align__(16) float g_kern[NSC * KSTR];                   // gathered kernels
__device__ __align__(16) __nv_bfloat16 g_ehh[(size_t)MTOT * KE + 64];// 6.2 MB [m][k] hi
__device__ __align__(16) __nv_bfloat16 g_ehl[(size_t)MTOT * KE + 64];// 6.2 MB [m][k] lo
__device__ __align__(16) float g_eke[NSC * 2 * EKE];                 // edge kernels f32
__device__ __align__(16) float g_part[(size_t)MAXCH * BM * NTOTAL];  // 41 MB partials
__device__ __align__(16) float g_tmpB[(size_t)MTOT * NTOTAL];        // 11 MB reduced
__device__ float  g_tmpA[NSC * NROW * OUTW];                         // 11 MB
__device__ int    g_n[NSC];
__device__ int    g_d0[NSC];
__device__ float  g_nsq[NSC];
__device__ double g_sden[NSC];
__device__ float  g_wt[OUTW * 40];
__device__ int    g_wst[OUTW];
__device__ int    g_wcnt[OUTW];
__device__ int    g_whi[OUTH * 2];
__device__ float  g_whw[OUTH * 2];
__device__ int    g_tk[7 * 2];
__device__ int    g_chk[MAXCH * 2];
__device__ int    g_chklen[MAXCH];
__device__ int    g_nchk;
__device__ int    g_tfirst[7];
__device__ int    g_tcnt[7];

// ---------------- setup (64-aligned K windows) ----------------
__global__ void k_setup() {
    int tid = threadIdx.x;
    if (tid < NSC) {
        double l2 = log10(2.0), lM = log10(204.0);
        double y = (tid == NSC - 1) ? lM : (l2 + (double)tid * ((lM - l2) / (double)(NSC - 1)));
        float  sf = (float)pow(10.0, y);
        double sd = (double)sf;
        int n = (int)ceil(sd * 16.0 + 1.0);
        int d0 = (4094 - n) / 2; if (d0 < 0) d0 = 0;
        g_n[tid]   = n;
        g_d0[tid]  = d0;
        g_nsq[tid] = -sqrtf(sf);
        g_sden[tid] = sd * (16.0 / 4095.0);
    }
    if (tid < OUTW) {
        double inv = 4096.0 / 224.0;
        double ks  = inv;
        double sfd = ((double)tid + 0.5) * inv - 0.5;
        int lo = (int)ceil(sfd - ks);  if (lo < 0) lo = 0;
        int hi = (int)floor(sfd + ks); if (hi > Tn - 1) hi = Tn - 1;
        double tot = 0.0;
        for (int i = lo; i <= hi; i++) {
            double w = 1.0 - fabs((double)i - sfd) / ks; if (w < 0.0) w = 0.0;
            tot += w;
        }
        int cnt = hi - lo + 1;
        g_wst[tid] = lo; g_wcnt[tid] = cnt;
        for (int j = 0; j < cnt; j++) {
            double w = 1.0 - fabs((double)(lo + j) - sfd) / ks; if (w < 0.0) w = 0.0;
            g_wt[tid * 40 + j] = (float)(w / tot);
        }
        for (int j = cnt; j < 40; j++) g_wt[tid * 40 + j] = 0.0f;
    }
    if (tid < OUTH) {
        double inv = 128.0 / 224.0;
        double sfd = ((double)tid + 0.5) * inv - 0.5;
        int ia = (int)floor(sfd);
        int i0 = ia, i1 = ia + 1;
        double w0 = 1.0 - (sfd - (double)ia);
        double w1 = sfd - (double)ia;
        bool v0 = (i0 >= 0 && i0 < NSC);
        bool v1 = (i1 >= 0 && i1 < NSC);
        double tot = (v0 ? w0 : 0.0) + (v1 ? w1 : 0.0);
        int   o0 = v0 ? i0 : (v1 ? i1 : 0);
        int   o1 = v1 ? i1 : (v0 ? i0 : 0);
        float f0 = v0 ? (float)(w0 / tot) : 0.0f;
        float f1 = v1 ? (float)(w1 / tot) : 0.0f;
        if (!v0 && v1) { f0 = (float)(w1 / tot); f1 = 0.0f; }
        g_whi[tid * 2 + 0] = o0; g_whi[tid * 2 + 1] = o1;
        g_whw[tid * 2 + 0] = f0; g_whw[tid * 2 + 1] = f1;
    }
    __syncthreads();
    if (tid < 7) {
        int smin = (BM * tid) / 7;
        int smax = (BM * tid + BM - 1) / 7; if (smax > NSC - 1) smax = NSC - 1;
        int lo = 1 << 30, hi = 0;
        for (int s = smin; s <= smax; s++) {
            for (int c = 0; c < 7; c++) {
                int A = g_d0[s] + g_wst[7 + c] - 128;
                int e = A + g_n[s] + g_wcnt[7 + c] - 1;
                int a0 = A - U0, e0 = e + 1 - U0;
                if (a0 < lo) lo = a0;
                if (e0 > hi) hi = e0;
            }
        }
        if (lo < 0) lo = 0;
        int hi64 = (hi + 63) & ~63; if (hi64 > KE) hi64 = KE;
        g_tk[tid * 2 + 0] = lo & ~63;
        g_tk[tid * 2 + 1] = hi64;
    }
    __syncthreads();
    if (tid == 0) {
        int nc = 0;
        for (int q = 0; q < 7; q++) {
            int mt = 6 - q;                       // heavy tiles first
            int klo = g_tk[mt * 2], khi = g_tk[mt * 2 + 1];
            g_tfirst[mt] = nc;
            int cnt = 0;
            for (int k = klo; k < khi && nc < MAXCH; k += KC) {
                int len = khi - k; if (len > KC) len = KC;
                g_chk[nc * 2 + 0] = mt;
                g_chk[nc * 2 + 1] = k;
                g_chklen[nc] = len;
                nc++; cnt++;
            }
            g_tcnt[mt] = cnt;
        }
        g_nchk = nc;
    }
}

// ---------------- dx helper ----------------
__device__ __forceinline__ float xp_val(const float* __restrict__ x, int b, int c, int p) {
    int i = p - PADL;
    if (i < 0) i = -i;
    else if (i >= Tn) i = 2 * (Tn - 1) - i;
    return x[((size_t)b * Tn + i) * Cn + c];
}

// ---------------- gather per scale + dx (grid-stride) fused ----------------
__global__ __launch_bounds__(256) void k_gatherdx(const float* __restrict__ psi,
                                                  const float* __restrict__ x) {
    int sc = blockIdx.x;
    int tid = threadIdx.x;
    int n = g_n[sc];
    double den = g_sden[sc];
    for (int k = tid; k < n; k += 256) {
        int m = n - 1 - k;                                  // flip
        int j = (int)floor((double)m / den);
        if (j < 0) j = 0;
        if (j > NPSI - 1) j = NPSI - 1;
        g_kern[sc * KSTR + k] = psi[j];
    }
    // dx slice
    for (int idx = sc * 256 + tid; idx < DXTOT; idx += NSC * 256) {
        int r = idx >> 13;
        int p = idx & (DXSTR - 1);
        int c = r / Bn, b = r % Bn;
        float v = 0.0f;
        if (p <= LP - 2) v = xp_val(x, b, c, p + 1) - xp_val(x, b, c, p);
        g_dx[idx] = v;
        __nv_bfloat16 h = __float2bfloat16(v);
        g_dxh[idx] = h;
        g_dxl[idx] = __float2bfloat16(v - __bfloat162float(h));
    }
}

// ---------------- build resize-folded kernels (bf16 hi/lo for interior) ----------------
__global__ __launch_bounds__(256) void k_ebuildc() {
    __shared__ float skern[KMAX];
    __shared__ float swt[40];
    int cls = blockIdx.x;
    int sc  = blockIdx.y;
    int tid = threadIdx.x;
    int n = g_n[sc], d0 = g_d0[sc];
    float nsq = g_nsq[sc];
    int wrep = (cls < 7) ? (7 + cls) : ((cls == 7) ? 0 : 223);
    int st = g_wst[wrep], cnt = g_wcnt[wrep];

    for (int k = tid; k < n; k += 256) skern[k] = g_kern[sc * KSTR + k];
    if (tid < 40) swt[tid] = g_wt[wrep * 40 + tid];
    __syncthreads();

    int len = n + cnt - 1;
    if (cls < 7) {
        int A = d0 + st - 128;
        int m = sc * 7 + cls;
        int p0 = A - U0;
        for (int v = tid; v < KE; v += 256) {
            int p = v - p0;
            float acc = 0.0f;
            if (p >= 0 && p < len) {
                int t0 = p - (n - 1); if (t0 < 0) t0 = 0;
                int t1 = p; if (t1 > cnt - 1) t1 = cnt - 1;
                for (int t = t0; t <= t1; t++) acc += swt[t] * skern[p - t];
                acc *= nsq;
            }
            __nv_bfloat16 h = __float2bfloat16(acc);
            g_ehh[(size_t)m * KE + v] = h;
            g_ehl[(size_t)m * KE + v] = __float2bfloat16(acc - __bfloat162float(h));
        }
    } else {
        int sh = (d0 + st) & 3;
        float* dst = g_eke + (size_t)(sc * 2 + (cls - 7)) * EKE;
        for (int v = tid; v < EKE; v += 256) {
            int p = v - sh;
            float acc = 0.0f;
            if (p >= 0 && p < len) {
                int t0 = p - (n - 1); if (t0 < 0) t0 = 0;
                int t1 = p; if (t1 > cnt - 1) t1 = cnt - 1;
                for (int t = t0; t <= t1; t++) acc += swt[t] * skern[p - t];
                acc *= nsq;
            }
            dst[v] = acc;
        }
    }
}

// ---------------- HMMA GEMM: D = AhBh + AhBl + AlBh, fp32 accum ----------------
#define MMA16816(d, a0, a1, a2, a3, b0, b1)                                         \
    asm volatile(                                                                   \
        "mma.sync.aligned.m16n8k16.row.col.f32.bf16.bf16.f32 "                      \
        "{%0,%1,%2,%3}, {%4,%5,%6,%7}, {%8,%9}, {%0,%1,%2,%3};"                     \
        : "+f"(d[0]), "+f"(d[1]), "+f"(d[2]), "+f"(d[3])                            \
        : "r"(a0), "r"(a1), "r"(a2), "r"(a3), "r"(b0), "r"(b1))

#define ASTRIDE 40            // bf16 per row (20 words, conflict-free, 16B-aligned)

__global__ __launch_bounds__(128) void k_gemm_mma() {
    __shared__ __nv_bfloat16 sAh[BM * ASTRIDE];
    __shared__ __nv_bfloat16 sAl[BM * ASTRIDE];
    __shared__ __nv_bfloat16 sBh[BN * ASTRIDE];
    __shared__ __nv_bfloat16 sBl[BN * ASTRIDE];

    int chunk = blockIdx.y;
    if (chunk >= g_nchk) return;
    int mt  = g_chk[chunk * 2 + 0];
    int klo = g_chk[chunk * 2 + 1];
    int nslab = g_chklen[chunk] >> 5;
    int nt = blockIdx.x;
    int m0 = mt * BM, n0 = nt * BN;
    int tid = threadIdx.x;
    int wid = tid >> 5, lane = tid & 31;
    int g = lane >> 2, tig = lane & 3;
    int R = wid * 32;                               // warp m-base in tile

    const unsigned* wAh = (const unsigned*)sAh;
    const unsigned* wAl = (const unsigned*)sAl;
    const unsigned* wBh = (const unsigned*)sBh;
    const unsigned* wBl = (const unsigned*)sBl;

    float acc[2][8][4];
    #pragma unroll
    for (int mi = 0; mi < 2; mi++)
        #pragma unroll
        for (int ni = 0; ni < 8; ni++) {
            acc[mi][ni][0] = 0.f; acc[mi][ni][1] = 0.f;
            acc[mi][ni][2] = 0.f; acc[mi][ni][3] = 0.f;
        }

    for (int s = 0; s < nslab; s++) {
        int koff = klo + s * 32;
        // stage A hi/lo: 128 rows x 32 bf16 (4 x 16B per row)
        for (int i = tid; i < 512; i += 128) {
            int row = i >> 2, q = i & 3;
            size_t gsrc = ((size_t)(m0 + row) * KE + koff + q * 8) * 2;   // bytes
            int dst = row * (ASTRIDE * 2) + q * 16;
            *(uint4*)((char*)sAh + dst) = *(const uint4*)((const char*)g_ehh + gsrc);
            *(uint4*)((char*)sAl + dst) = *(const uint4*)((const char*)g_ehl + gsrc);
        }
        // stage B hi/lo: 64 n-rows x 32 bf16
        for (int i = tid; i < 256; i += 128) {
            int row = i >> 2, q = i & 3;
            int n = n0 + row;
            int drow = n >> 5, j = n & 31;
            size_t gsrc = ((size_t)drow * DXSTR + U0 + koff + 128 * j + q * 8) * 2;
            int dst = row * (ASTRIDE * 2) + q * 16;
            *(uint4*)((char*)sBh + dst) = *(const uint4*)((const char*)g_dxh + gsrc);
            *(uint4*)((char*)sBl + dst) = *(const uint4*)((const char*)g_dxl + gsrc);
        }
        __syncthreads();

        #pragma unroll
        for (int ks = 0; ks < 2; ks++) {
            int kw = ks * 8;                        // word offset (16 bf16)
            unsigned aH[2][4], aL[2][4];
            #pragma unroll
            for (int mi = 0; mi < 2; mi++) {
                int r0 = (R + mi * 16 + g) * 20 + tig + kw;
                int r8 = r0 + 8 * 20;
                aH[mi][0] = wAh[r0];     aH[mi][1] = wAh[r8];
                aH[mi][2] = wAh[r0 + 4]; aH[mi][3] = wAh[r8 + 4];
                aL[mi][0] = wAl[r0];     aL[mi][1] = wAl[r8];
                aL[mi][2] = wAl[r0 + 4]; aL[mi][3] = wAl[r8 + 4];
            }
            #pragma unroll
            for (int ni = 0; ni < 8; ni++) {
                int b0i = (ni * 8 + g) * 20 + tig + kw;
                unsigned bh0 = wBh[b0i], bh1 = wBh[b0i + 4];
                unsigned bl0 = wBl[b0i], bl1 = wBl[b0i + 4];
                #pragma unroll
                for (int mi = 0; mi < 2; mi++) {
                    MMA16816(acc[mi][ni], aH[mi][0], aH[mi][1], aH[mi][2], aH[mi][3], bh0, bh1);
                    MMA16816(acc[mi][ni], aH[mi][0], aH[mi][1], aH[mi][2], aH[mi][3], bl0, bl1);
                    MMA16816(acc[mi][ni], aL[mi][0], aL[mi][1], aL[mi][2], aL[mi][3], bh0, bh1);
                }
            }
        }
        __syncthreads();
    }

    // epilogue: c0,c1 -> row g; c2,c3 -> row g+8
    float* pp = g_part + ((size_t)chunk * BM) * NTOTAL + n0;
    #pragma unroll
    for (int mi = 0; mi < 2; mi++) {
        int mrow = R + mi * 16 + g;
        #pragma unroll
        for (int ni = 0; ni < 8; ni++) {
            int nc = ni * 8 + tig * 2;
            *(float2*)(pp + (size_t)mrow * NTOTAL + nc) =
                make_float2(acc[mi][ni][0], acc[mi][ni][1]);
            *(float2*)(pp + (size_t)(mrow + 8) * NTOTAL + nc) =
                make_float2(acc[mi][ni][2], acc[mi][ni][3]);
        }
    }
}

// ---------------- split-K reduction (coalesced, m-major out) ----------------
__global__ __launch_bounds__(256) void k_red() {
    int idx = blockIdx.x * 256 + threadIdx.x;
    if (idx >= MTOT * (NTOTAL / 4)) return;
    int m = idx / (NTOTAL / 4);
    int q = idx - m * (NTOTAL / 4);
    int n = q * 4;
    int mt = m >> 7, ml = m & 127;
    int first = g_tfirst[mt], cnt = g_tcnt[mt];
    float4 s = make_float4(0.f, 0.f, 0.f, 0.f);
    for (int c = 0; c < cnt; c++) {
        const float4 v = *(const float4*)(g_part + ((size_t)(first + c) * BM + ml) * NTOTAL + n);
        s.x += v.x; s.y += v.y; s.z += v.z; s.w += v.w;
    }
    *(float4*)(g_tmpB + (size_t)m * NTOTAL + n) = s;
}

// ---------------- permute tmpB -> tmpA ----------------
__global__ __launch_bounds__(224) void k_tr2() {
    __shared__ float sm[224];
    int sc  = blockIdx.x;
    int row = blockIdx.y;
    int t = threadIdx.x;
    int cc = t >> 5, jj = t & 31;
    sm[cc * 32 + jj] = g_tmpB[(size_t)(sc * 7 + cc) * NTOTAL + row * 32 + jj];
    __syncthreads();
    int w = t;
    int j2 = w / 7, c2 = w - j2 * 7;
    g_tmpA[(sc * NROW + row) * OUTW + w] = sm[c2 * 32 + j2];
}

// ---------------- exact fixup for clipped edge columns w=0, w=223 ----------------
__global__ void k_fixup() {
    __shared__ float se[EKE];
    int e  = blockIdx.x;
    int sc = blockIdx.y;
    int tid = threadIdx.x;
    int wE = e ? 223 : 0;
    int n = g_n[sc], d0 = g_d0[sc];
    int st = g_wst[wE], cnt = g_wcnt[wE];
    int base = (d0 + st) & ~3;
    int sh = (d0 + st) & 3;
    int qmax = sh + n + cnt - 1;

    const float* esrc = g_eke + (size_t)(sc * 2 + e) * EKE;
    for (int i = tid * 4; i < EKE; i += 1024)
        *(float4*)(se + i) = *(const float4*)(esrc + i);
    __syncthreads();

    int wi = tid >> 5, lane = tid & 31;
    for (int row = wi; row < NROW; row += 8) {
        const float* dxr = g_dx + (size_t)row * DXSTR + base;
        float p = 0.f;
        for (int q = lane * 4; q < qmax; q += 128) {
            float4 d = *(const float4*)(dxr + q);
            float4 ev = *(const float4*)(se + q);
            p = fmaf(d.x, ev.x, fmaf(d.y, ev.y, fmaf(d.z, ev.z, fmaf(d.w, ev.w, p))));
        }
        #pragma unroll
        for (int o = 16; o > 0; o >>= 1) p += __shfl_xor_sync(0xffffffffu, p, o);
        if (lane == 0) g_tmpA[(sc * NROW + row) * OUTW + wE] = p;
    }
}

// ---------------- resize stage B: scale axis 128 -> 224 ----------------
__global__ void k_resize_h(float* __restrict__ out) {
    int idx = blockIdx.x * blockDim.x + threadIdx.x;
    if (idx >= OUTN) return;
    int c = idx % Cn;
    int w = (idx / Cn) % OUTW;
    int h = (idx / (Cn * OUTW)) % OUTH;
    int b = idx / (Cn * OUTW * OUTH);
    int i0 = g_whi[h * 2 + 0], i1 = g_whi[h * 2 + 1];
    float f0 = g_whw[h * 2 + 0], f1 = g_whw[h * 2 + 1];
    int rb = (c * Bn + b) * OUTW + w;
    out[idx] = f0 * g_tmpA[i0 * NROW * OUTW + rb] + f1 * g_tmpA[i1 * NROW * OUTW + rb];
}

// ---------------- launch ----------------
extern "C" void kernel_launch(void* const* d_in, const int* in_sizes, int n_in,
                              void* d_out, int out_size) {
    const float* x   = (const float*)d_in[0];       // (32, 4096, 3) f32
    const float* psi = (const float*)d_in[1];       // (4096,) f32
    float* out = (float*)d_out;

    k_setup<<<1, 256>>>();
    k_gatherdx<<<NSC, 256>>>(psi, x);
    k_ebuildc<<<dim3(9, NSC), 256>>>();
    k_gemm_mma<<<dim3(48, MAXCH), 128>>>();          // launch index 3 -> ncu slot
    k_red<<<(MTOT * (NTOTAL / 4) + 255) / 256, 256>>>();
    k_tr2<<<dim3(NSC, NROW), 224>>>();
    k_fixup<<<dim3(2, NSC), 256>>>();
    k_resize_h<<<(OUTN + 255) / 256, 256>>>(out);
}

// round 15
// speedup vs baseline: 1.5280x; 1.0374x over previous
#include <cuda_runtime.h>
#include <cuda_bf16.h>
#include <math.h>

// ---------------- static configuration ----------------
#define Bn     32
#define Tn     4096
#define Cn     3
#define NSC    128
#define NPSI   4096
#define PADL   2047
#define LP     8190           // Tn + 2*PADL
#define DXSTR  8192
#define NROW   96             // Cn * Bn
#define OUTH   224
#define OUTW   224
#define OUTN   (Bn*OUTH*OUTW*Cn)

#define U0     384            // global u-grid origin
#define KE     3456           // Ê u-extent (64-aligned)
#define MTOT   896            // 128 scales x 7 interior classes
#define KMAX   3268           // >= max wavelet kernel length 3265
#define KSTR   3280           // g_kern row stride
#define EKE    3328           // edge-kernel stride (fixup)

#define BM     128
#define BN     64
#define KC     512            // split-K chunk (16 slabs of 32)
#define MAXCH  26             // chunk table capacity (real ~19)
#define NTOTAL 3072           // 96 rows x 32 j
#define DXTOT  (NROW * DXSTR)

#define BUFSZ  30720          // one staging buffer: Ah(10240)+Al(10240)+Bh(5120)+Bl(5120)
#define AHo    0
#define ALo    10240
#define BHo    20480
#define BLo    25600

// ---------------- device scratch ----------------
__device__ __align__(16) float g_dx[DXTOT + 4096];                   // 3 MB f32 (fixup)
__device__ __align__(16) __nv_bfloat16 g_dxh[DXTOT + 4096];          // 1.5 MB
__device__ __align__(16) __nv_bfloat16 g_dxl[DXTOT + 4096];          // 1.5 MB
__device__ __align__(16) float g_kern[NSC * KSTR];                   // gathered kernels
__device__ __align__(16) __nv_bfloat16 g_ehh[(size_t)MTOT * KE + 64];// 6.2 MB [m][k] hi
__device__ __align__(16) __nv_bfloat16 g_ehl[(size_t)MTOT * KE + 64];// 6.2 MB [m][k] lo
__device__ __align__(16) float g_eke[NSC * 2 * EKE];                 // edge kernels f32
__device__ __align__(16) float g_part[(size_t)MAXCH * BM * NTOTAL];  // 41 MB partials
__device__ float  g_tmpA[NSC * NROW * OUTW];                         // 11 MB
__device__ int    g_n[NSC];
__device__ int    g_d0[NSC];
__device__ float  g_nsq[NSC];
__device__ double g_sden[NSC];
__device__ float  g_wt[OUTW * 40];
__device__ int    g_wst[OUTW];
__device__ int    g_wcnt[OUTW];
__device__ int    g_whi[OUTH * 2];
__device__ float  g_whw[OUTH * 2];
__device__ int    g_tk[7 * 2];
__device__ int    g_chk[MAXCH * 2];
__device__ int    g_chklen[MAXCH];
__device__ int    g_nchk;
__device__ int    g_tfirst[7];
__device__ int    g_tcnt[7];

// ---------------- helpers ----------------
__device__ __forceinline__ unsigned smem_u32(const void* p) {
    unsigned a;
    asm("{ .reg .u64 t; cvta.to.shared.u64 t, %1; cvt.u32.u64 %0, t; }" : "=r"(a) : "l"(p));
    return a;
}
#define CP16(dst, src) \
    asm volatile("cp.async.cg.shared.global [%0], [%1], 16;" :: "r"(dst), "l"(src) : "memory")
#define CP_COMMIT() asm volatile("cp.async.commit_group;" ::: "memory")
#define CP_WAIT0()  asm volatile("cp.async.wait_group 0;" ::: "memory")

// ---------------- setup (64-aligned K windows) ----------------
__global__ void k_setup() {
    int tid = threadIdx.x;
    if (tid < NSC) {
        double l2 = log10(2.0), lM = log10(204.0);
        double y = (tid == NSC - 1) ? lM : (l2 + (double)tid * ((lM - l2) / (double)(NSC - 1)));
        float  sf = (float)pow(10.0, y);
        double sd = (double)sf;
        int n = (int)ceil(sd * 16.0 + 1.0);
        int d0 = (4094 - n) / 2; if (d0 < 0) d0 = 0;
        g_n[tid]   = n;
        g_d0[tid]  = d0;
        g_nsq[tid] = -sqrtf(sf);
        g_sden[tid] = sd * (16.0 / 4095.0);
    }
    if (tid < OUTW) {
        double inv = 4096.0 / 224.0;
        double ks  = inv;
        double sfd = ((double)tid + 0.5) * inv - 0.5;
        int lo = (int)ceil(sfd - ks);  if (lo < 0) lo = 0;
        int hi = (int)floor(sfd + ks); if (hi > Tn - 1) hi = Tn - 1;
        double tot = 0.0;
        for (int i = lo; i <= hi; i++) {
            double w = 1.0 - fabs((double)i - sfd) / ks; if (w < 0.0) w = 0.0;
            tot += w;
        }
        int cnt = hi - lo + 1;
        g_wst[tid] = lo; g_wcnt[tid] = cnt;
        for (int j = 0; j < cnt; j++) {
            double w = 1.0 - fabs((double)(lo + j) - sfd) / ks; if (w < 0.0) w = 0.0;
            g_wt[tid * 40 + j] = (float)(w / tot);
        }
        for (int j = cnt; j < 40; j++) g_wt[tid * 40 + j] = 0.0f;
    }
    if (tid < OUTH) {
        double inv = 128.0 / 224.0;
        double sfd = ((double)tid + 0.5) * inv - 0.5;
        int ia = (int)floor(sfd);
        int i0 = ia, i1 = ia + 1;
        double w0 = 1.0 - (sfd - (double)ia);
        double w1 = sfd - (double)ia;
        bool v0 = (i0 >= 0 && i0 < NSC);
        bool v1 = (i1 >= 0 && i1 < NSC);
        double tot = (v0 ? w0 : 0.0) + (v1 ? w1 : 0.0);
        int   o0 = v0 ? i0 : (v1 ? i1 : 0);
        int   o1 = v1 ? i1 : (v0 ? i0 : 0);
        float f0 = v0 ? (float)(w0 / tot) : 0.0f;
        float f1 = v1 ? (float)(w1 / tot) : 0.0f;
        if (!v0 && v1) { f0 = (float)(w1 / tot); f1 = 0.0f; }
        g_whi[tid * 2 + 0] = o0; g_whi[tid * 2 + 1] = o1;
        g_whw[tid * 2 + 0] = f0; g_whw[tid * 2 + 1] = f1;
    }
    __syncthreads();
    if (tid < 7) {
        int smin = (BM * tid) / 7;
        int smax = (BM * tid + BM - 1) / 7; if (smax > NSC - 1) smax = NSC - 1;
        int lo = 1 << 30, hi = 0;
        for (int s = smin; s <= smax; s++) {
            for (int c = 0; c < 7; c++) {
                int A = g_d0[s] + g_wst[7 + c] - 128;
                int e = A + g_n[s] + g_wcnt[7 + c] - 1;
                int a0 = A - U0, e0 = e + 1 - U0;
                if (a0 < lo) lo = a0;
                if (e0 > hi) hi = e0;
            }
        }
        if (lo < 0) lo = 0;
        int hi64 = (hi + 63) & ~63; if (hi64 > KE) hi64 = KE;
        g_tk[tid * 2 + 0] = lo & ~63;
        g_tk[tid * 2 + 1] = hi64;
    }
    __syncthreads();
    if (tid == 0) {
        int nc = 0;
        for (int q = 0; q < 7; q++) {
            int mt = 6 - q;                       // heavy tiles first
            int klo = g_tk[mt * 2], khi = g_tk[mt * 2 + 1];
            g_tfirst[mt] = nc;
            int cnt = 0;
            for (int k = klo; k < khi && nc < MAXCH; k += KC) {
                int len = khi - k; if (len > KC) len = KC;
                g_chk[nc * 2 + 0] = mt;
                g_chk[nc * 2 + 1] = k;
                g_chklen[nc] = len;
                nc++; cnt++;
            }
            g_tcnt[mt] = cnt;
        }
        g_nchk = nc;
    }
}

// ---------------- dx helper ----------------
__device__ __forceinline__ float xp_val(const float* __restrict__ x, int b, int c, int p) {
    int i = p - PADL;
    if (i < 0) i = -i;
    else if (i >= Tn) i = 2 * (Tn - 1) - i;
    return x[((size_t)b * Tn + i) * Cn + c];
}

// ---------------- gather per scale + dx (grid-stride) fused ----------------
__global__ __launch_bounds__(256) void k_gatherdx(const float* __restrict__ psi,
                                                  const float* __restrict__ x) {
    int sc = blockIdx.x;
    int tid = threadIdx.x;
    int n = g_n[sc];
    double den = g_sden[sc];
    for (int k = tid; k < n; k += 256) {
        int m = n - 1 - k;                                  // flip
        int j = (int)floor((double)m / den);
        if (j < 0) j = 0;
        if (j > NPSI - 1) j = NPSI - 1;
        g_kern[sc * KSTR + k] = psi[j];
    }
    for (int idx = sc * 256 + tid; idx < DXTOT; idx += NSC * 256) {
        int r = idx >> 13;
        int p = idx & (DXSTR - 1);
        int c = r / Bn, b = r % Bn;
        float v = 0.0f;
        if (p <= LP - 2) v = xp_val(x, b, c, p + 1) - xp_val(x, b, c, p);
        g_dx[idx] = v;
        __nv_bfloat16 h = __float2bfloat16(v);
        g_dxh[idx] = h;
        g_dxl[idx] = __float2bfloat16(v - __bfloat162float(h));
    }
}

// ---------------- build resize-folded kernels (bf16 hi/lo for interior) ----------------
__global__ __launch_bounds__(256) void k_ebuildc() {
    __shared__ float skern[KMAX];
    __shared__ float swt[40];
    int cls = blockIdx.x;
    int sc  = blockIdx.y;
    int tid = threadIdx.x;
    int n = g_n[sc], d0 = g_d0[sc];
    float nsq = g_nsq[sc];
    int wrep = (cls < 7) ? (7 + cls) : ((cls == 7) ? 0 : 223);
    int st = g_wst[wrep], cnt = g_wcnt[wrep];

    for (int k = tid; k < n; k += 256) skern[k] = g_kern[sc * KSTR + k];
    if (tid < 40) swt[tid] = g_wt[wrep * 40 + tid];
    __syncthreads();

    int len = n + cnt - 1;
    if (cls < 7) {
        int A = d0 + st - 128;
        int m = sc * 7 + cls;
        int p0 = A - U0;
        for (int v = tid; v < KE; v += 256) {
            int p = v - p0;
            float acc = 0.0f;
            if (p >= 0 && p < len) {
                int t0 = p - (n - 1); if (t0 < 0) t0 = 0;
                int t1 = p; if (t1 > cnt - 1) t1 = cnt - 1;
                for (int t = t0; t <= t1; t++) acc += swt[t] * skern[p - t];
                acc *= nsq;
            }
            __nv_bfloat16 h = __float2bfloat16(acc);
            g_ehh[(size_t)m * KE + v] = h;
            g_ehl[(size_t)m * KE + v] = __float2bfloat16(acc - __bfloat162float(h));
        }
    } else {
        int sh = (d0 + st) & 3;
        float* dst = g_eke + (size_t)(sc * 2 + (cls - 7)) * EKE;
        for (int v = tid; v < EKE; v += 256) {
            int p = v - sh;
            float acc = 0.0f;
            if (p >= 0 && p < len) {
                int t0 = p - (n - 1); if (t0 < 0) t0 = 0;
                int t1 = p; if (t1 > cnt - 1) t1 = cnt - 1;
                for (int t = t0; t <= t1; t++) acc += swt[t] * skern[p - t];
                acc *= nsq;
            }
            dst[v] = acc;
        }
    }
}

// ---------------- HMMA GEMM, cp.async double-buffered ----------------
#define MMA16816(d, a0, a1, a2, a3, b0, b1)                                         \
    asm volatile(                                                                   \
        "mma.sync.aligned.m16n8k16.row.col.f32.bf16.bf16.f32 "                      \
        "{%0,%1,%2,%3}, {%4,%5,%6,%7}, {%8,%9}, {%0,%1,%2,%3};"                     \
        : "+f"(d[0]), "+f"(d[1]), "+f"(d[2]), "+f"(d[3])                            \
        : "r"(a0), "r"(a1), "r"(a2), "r"(a3), "r"(b0), "r"(b1))

__global__ __launch_bounds__(128) void k_gemm_mma() {
    extern __shared__ char smc[];

    int chunk = blockIdx.y;
    if (chunk >= g_nchk) return;
    int mt  = g_chk[chunk * 2 + 0];
    int klo = g_chk[chunk * 2 + 1];
    int nslab = g_chklen[chunk] >> 5;
    int nt = blockIdx.x;
    int m0 = mt * BM, n0 = nt * BN;
    int tid = threadIdx.x;
    int wid = tid >> 5, lane = tid & 31;
    int g = lane >> 2, tig = lane & 3;
    int R = wid * 32;

    unsigned sbase = smem_u32(smc);

    // precomputed staging coords for this thread
    int arow = tid >> 2, aq = tid & 3;              // covers 32 rows/pass x 4 passes
    int brow = tid >> 2;                             // 0..31 (two passes of 32 n-rows)

    // stage slab s into buffer buf (all cp.async, one commit group)
    auto stage = [&](int s, int buf) {
        int koff = klo + s * 32;
        unsigned sb = sbase + buf * BUFSZ;
        #pragma unroll
        for (int pass = 0; pass < 4; pass++) {
            int row = arow + pass * 32;
            size_t gsrc = ((size_t)(m0 + row) * KE + koff + aq * 8) * 2;
            unsigned dst = sb + AHo + row * 80 + aq * 16;
            CP16(dst, (const char*)g_ehh + gsrc);
            CP16(dst + (ALo - AHo), (const char*)g_ehl + gsrc);
        }
        #pragma unroll
        for (int pass = 0; pass < 2; pass++) {
            int row = brow + pass * 32;
            int n = n0 + row;
            int drow = n >> 5, j = n & 31;
            size_t gsrc = ((size_t)drow * DXSTR + U0 + koff + 128 * j + aq * 8) * 2;
            unsigned dst = sb + BHo + row * 80 + aq * 16;
            CP16(dst, (const char*)g_dxh + gsrc);
            CP16(dst + (BLo - BHo), (const char*)g_dxl + gsrc);
        }
        CP_COMMIT();
    };

    float acc[2][8][4];
    #pragma unroll
    for (int mi = 0; mi < 2; mi++)
        #pragma unroll
        for (int ni = 0; ni < 8; ni++) {
            acc[mi][ni][0] = 0.f; acc[mi][ni][1] = 0.f;
            acc[mi][ni][2] = 0.f; acc[mi][ni][3] = 0.f;
        }

    stage(0, 0);
    CP_WAIT0();
    __syncthreads();

    for (int s = 0; s < nslab; s++) {
        int cur = s & 1;
        if (s + 1 < nslab) stage(s + 1, cur ^ 1);

        const unsigned* wAh = (const unsigned*)(smc + cur * BUFSZ + AHo);
        const unsigned* wAl = (const unsigned*)(smc + cur * BUFSZ + ALo);
        const unsigned* wBh = (const unsigned*)(smc + cur * BUFSZ + BHo);
        const unsigned* wBl = (const unsigned*)(smc + cur * BUFSZ + BLo);

        #pragma unroll
        for (int ks = 0; ks < 2; ks++) {
            int kw = ks * 8;
            unsigned aH[2][4], aL[2][4];
            #pragma unroll
            for (int mi = 0; mi < 2; mi++) {
                int r0 = (R + mi * 16 + g) * 20 + tig + kw;
                int r8 = r0 + 8 * 20;
                aH[mi][0] = wAh[r0];     aH[mi][1] = wAh[r8];
                aH[mi][2] = wAh[r0 + 4]; aH[mi][3] = wAh[r8 + 4];
                aL[mi][0] = wAl[r0];     aL[mi][1] = wAl[r8];
                aL[mi][2] = wAl[r0 + 4]; aL[mi][3] = wAl[r8 + 4];
            }
            #pragma unroll
            for (int ni = 0; ni < 8; ni++) {
                int b0i = (ni * 8 + g) * 20 + tig + kw;
                unsigned bh0 = wBh[b0i], bh1 = wBh[b0i + 4];
                unsigned bl0 = wBl[b0i], bl1 = wBl[b0i + 4];
                #pragma unroll
                for (int mi = 0; mi < 2; mi++) {
                    MMA16816(acc[mi][ni], aH[mi][0], aH[mi][1], aH[mi][2], aH[mi][3], bh0, bh1);
                    MMA16816(acc[mi][ni], aH[mi][0], aH[mi][1], aH[mi][2], aH[mi][3], bl0, bl1);
                    MMA16816(acc[mi][ni], aL[mi][0], aL[mi][1], aL[mi][2], aL[mi][3], bh0, bh1);
                }
            }
        }

        if (s + 1 < nslab) CP_WAIT0();
        __syncthreads();
    }

    float* pp = g_part + ((size_t)chunk * BM) * NTOTAL + n0;
    #pragma unroll
    for (int mi = 0; mi < 2; mi++) {
        int mrow = R + mi * 16 + g;
        #pragma unroll
        for (int ni = 0; ni < 8; ni++) {
            int nc = ni * 8 + tig * 2;
            *(float2*)(pp + (size_t)mrow * NTOTAL + nc) =
                make_float2(acc[mi][ni][0], acc[mi][ni][1]);
            *(float2*)(pp + (size_t)(mrow + 8) * NTOTAL + nc) =
                make_float2(acc[mi][ni][2], acc[mi][ni][3]);
        }
    }
}

// ---------------- fused split-K reduction + permute into g_tmpA ----------------
__global__ __launch_bounds__(224) void k_redtr2() {
    __shared__ float sm[224];
    int sc  = blockIdx.x;
    int row = blockIdx.y;
    int t = threadIdx.x;
    int cc = t >> 5, jj = t & 31;
    int m = sc * 7 + cc;
    int mt = m >> 7, ml = m & 127;
    int first = g_tfirst[mt], cnt = g_tcnt[mt];
    float s = 0.f;
    for (int c = 0; c < cnt; c++)
        s += g_part[((size_t)(first + c) * BM + ml) * NTOTAL + row * 32 + jj];
    sm[cc * 32 + jj] = s;
    __syncthreads();
    int w = t;
    int j2 = w / 7, c2 = w - j2 * 7;
    g_tmpA[(sc * NROW + row) * OUTW + w] = sm[c2 * 32 + j2];
}

// ---------------- exact fixup for clipped edge columns w=0, w=223 ----------------
__global__ void k_fixup() {
    __shared__ float se[EKE];
    int e  = blockIdx.x;
    int sc = blockIdx.y;
    int tid = threadIdx.x;
    int wE = e ? 223 : 0;
    int n = g_n[sc], d0 = g_d0[sc];
    int st = g_wst[wE], cnt = g_wcnt[wE];
    int base = (d0 + st) & ~3;
    int sh = (d0 + st) & 3;
    int qmax = sh + n + cnt - 1;

    const float* esrc = g_eke + (size_t)(sc * 2 + e) * EKE;
    for (int i = tid * 4; i < EKE; i += 1024)
        *(float4*)(se + i) = *(const float4*)(esrc + i);
    __syncthreads();

    int wi = tid >> 5, lane = tid & 31;
    for (int row = wi; row < NROW; row += 8) {
        const float* dxr = g_dx + (size_t)row * DXSTR + base;
        float p = 0.f;
        for (int q = lane * 4; q < qmax; q += 128) {
            float4 d = *(const float4*)(dxr + q);
            float4 ev = *(const float4*)(se + q);
            p = fmaf(d.x, ev.x, fmaf(d.y, ev.y, fmaf(d.z, ev.z, fmaf(d.w, ev.w, p))));
        }
        #pragma unroll
        for (int o = 16; o > 0; o >>= 1) p += __shfl_xor_sync(0xffffffffu, p, o);
        if (lane == 0) g_tmpA[(sc * NROW + row) * OUTW + wE] = p;
    }
}

// ---------------- resize stage B: scale axis 128 -> 224 ----------------
__global__ void k_resize_h(float* __restrict__ out) {
    int idx = blockIdx.x * blockDim.x + threadIdx.x;
    if (idx >= OUTN) return;
    int c = idx % Cn;
    int w = (idx / Cn) % OUTW;
    int h = (idx / (Cn * OUTW)) % OUTH;
    int b = idx / (Cn * OUTW * OUTH);
    int i0 = g_whi[h * 2 + 0], i1 = g_whi[h * 2 + 1];
    float f0 = g_whw[h * 2 + 0], f1 = g_whw[h * 2 + 1];
    int rb = (c * Bn + b) * OUTW + w;
    out[idx] = f0 * g_tmpA[i0 * NROW * OUTW + rb] + f1 * g_tmpA[i1 * NROW * OUTW + rb];
}

// ---------------- launch ----------------
extern "C" void kernel_launch(void* const* d_in, const int* in_sizes, int n_in,
                              void* d_out, int out_size) {
    const float* x   = (const float*)d_in[0];       // (32, 4096, 3) f32
    const float* psi = (const float*)d_in[1];       // (4096,) f32
    float* out = (float*)d_out;

    static int smem_set = 0;
    if (!smem_set) {
        cudaFuncSetAttribute(k_gemm_mma, cudaFuncAttributeMaxDynamicSharedMemorySize,
                             2 * BUFSZ);
        smem_set = 1;
    }

    k_setup<<<1, 256>>>();
    k_gatherdx<<<NSC, 256>>>(psi, x);
    k_ebuildc<<<dim3(9, NSC), 256>>>();
    k_gemm_mma<<<dim3(48, MAXCH), 128, 2 * BUFSZ>>>();   // launch index 3 -> ncu slot
    k_redtr2<<<dim3(NSC, NROW), 224>>>();
    k_fixup<<<dim3(2, NSC), 256>>>();
    k_resize_h<<<(OUTN + 255) / 256, 256>>>(out);
}